// round 1
// baseline (speedup 1.0000x reference)
#include <cuda_runtime.h>
#include <cstdint>

// Problem constants (fixed by the dataset)
#define ROWS        8192
#define COLS        8192
#define NUMEL       (ROWS * COLS)            // 67,108,864
#define CENTROID_LEN 4
#define NGROUPS     (NUMEL / CENTROID_LEN)   // 16,777,216 groups of 4 floats
#define HALF_GROUPS (NGROUPS / 2)            // 8,388,608 -> codebook boundary
#define NQUADS      (NGROUPS / 4)            // 4,194,304 (each thread: 4 groups)
#define CB_ROWS     512                      // 2 codebooks * 256 centroids

__global__ __launch_bounds__(256, 8)
void dequant_kernel(const float4* __restrict__ codebooks,   // 512 x float4 (8KB)
                    const float*  __restrict__ scales,      // numel/64 floats
                    const int4*   __restrict__ codes,       // NQUADS int4
                    float4*       __restrict__ out)         // NGROUPS float4
{
    __shared__ float4 scb[CB_ROWS];

    // Stage the 8KB codebook into shared memory (2 float4 per thread @256thr).
    int t = threadIdx.x;
    #pragma unroll
    for (int i = t; i < CB_ROWS; i += 256)
        scb[i] = codebooks[i];
    __syncthreads();

    unsigned int quad = blockIdx.x * 256u + t;   // 0 .. NQUADS-1, exact grid
    // 4 consecutive groups handled by this thread
    unsigned int g0 = quad * 4u;

    int4 c = codes[quad];                        // 16B coalesced load

    // Codebook select: groups [0, HALF) -> book 0, [HALF, NGROUPS) -> book 1.
    // HALF_GROUPS % 4 == 0, so all 4 groups of a quad share one book.
    int base = (g0 >= HALF_GROUPS) ? 256 : 0;

    // scale per 64 output elems == per 16 groups; quad (4 groups, g0 % 4 == 0)
    // never straddles a 16-group block boundary.
    float s = __ldg(&scales[g0 >> 4]);

    float4 v0 = scb[base + c.x];
    float4 v1 = scb[base + c.y];
    float4 v2 = scb[base + c.z];
    float4 v3 = scb[base + c.w];

    v0.x *= s; v0.y *= s; v0.z *= s; v0.w *= s;
    v1.x *= s; v1.y *= s; v1.z *= s; v1.w *= s;
    v2.x *= s; v2.y *= s; v2.z *= s; v2.w *= s;
    v3.x *= s; v3.y *= s; v3.z *= s; v3.w *= s;

    float4* o = out + (size_t)g0;
    o[0] = v0;
    o[1] = v1;
    o[2] = v2;
    o[3] = v3;
}

extern "C" void kernel_launch(void* const* d_in, const int* in_sizes, int n_in,
                              void* d_out, int out_size)
{
    const float4* codebooks = (const float4*)d_in[0];  // [2,256,4] fp32
    const float*  scales    = (const float*) d_in[1];  // [numel/64, 1] fp32
    const int4*   codes     = (const int4*)  d_in[2];  // [2, numel/8] int32
    float4*       out       = (float4*)d_out;          // [8192, 8192] fp32

    dim3 block(256);
    dim3 grid(NQUADS / 256);   // 16384 blocks, exact coverage
    dequant_kernel<<<grid, block>>>(codebooks, scales, codes, out);
}

// round 2
// speedup vs baseline: 1.1056x; 1.1056x over previous
#include <cuda_runtime.h>
#include <cstdint>

// Problem constants (fixed by the dataset)
#define ROWS        8192
#define COLS        8192
#define NUMEL       (ROWS * COLS)            // 67,108,864
#define CENTROID_LEN 4
#define NGROUPS     (NUMEL / CENTROID_LEN)   // 16,777,216 groups of 4 floats
#define HALF_GROUPS (NGROUPS / 2)            // 8,388,608 -> codebook boundary
#define NQUADS      (NGROUPS / 4)            // 4,194,304 quads (4 groups each)
#define CB_ROWS     512                      // 2 codebooks * 256 centroids

#define NCTA 2048
#define TPB  256
#define QPT  (NQUADS / (NCTA * TPB))         // 8 quads per thread
#define BATCH 4                              // unrolled loads in flight

__global__ __launch_bounds__(TPB, 4)
void dequant_kernel(const float4* __restrict__ codebooks,   // 512 x float4 (8KB)
                    const float*  __restrict__ scales,      // numel/64 floats
                    const int4*   __restrict__ codes,       // NQUADS int4
                    float4*       __restrict__ out)         // NGROUPS float4
{
    __shared__ float4 scb[CB_ROWS];

    int t = threadIdx.x;
    #pragma unroll
    for (int i = t; i < CB_ROWS; i += TPB)
        scb[i] = codebooks[i];
    __syncthreads();

    // This block owns quads [blockStart, blockStart + TPB*QPT).
    unsigned int blockStart = blockIdx.x * (TPB * QPT);

    // Codebook half: block range (2048 quads) never straddles HALF boundary
    // (HALF_GROUPS/4 = 2,097,152 is a multiple of 2048) -> uniform base.
    const float4* cb = scb + ((blockStart * 4u >= HALF_GROUPS) ? 256 : 0);

    #pragma unroll
    for (int ii = 0; ii < QPT; ii += BATCH) {
        unsigned int q[BATCH];
        int4  c[BATCH];
        float s[BATCH];

        // Issue all independent global loads first (MLP = BATCH+scales).
        #pragma unroll
        for (int j = 0; j < BATCH; j++) {
            q[j] = blockStart + (unsigned)(ii + j) * TPB + t;
            c[j] = codes[q[j]];
            s[j] = __ldg(&scales[q[j]]);   // scale idx = (q*4)>>4 = q>>2... see below
        }
        // NOTE on scales: scale block = 64 elems = 16 groups = 4 quads,
        // so index = q >> 2. Recompute properly:
        #pragma unroll
        for (int j = 0; j < BATCH; j++)
            s[j] = __ldg(&scales[q[j] >> 2]);

        #pragma unroll
        for (int j = 0; j < BATCH; j++) {
            float4 v0 = cb[c[j].x];
            float4 v1 = cb[c[j].y];
            float4 v2 = cb[c[j].z];
            float4 v3 = cb[c[j].w];
            float sj = s[j];
            v0.x *= sj; v0.y *= sj; v0.z *= sj; v0.w *= sj;
            v1.x *= sj; v1.y *= sj; v1.z *= sj; v1.w *= sj;
            v2.x *= sj; v2.y *= sj; v2.z *= sj; v2.w *= sj;
            v3.x *= sj; v3.y *= sj; v3.z *= sj; v3.w *= sj;

            float4* o = out + (size_t)q[j] * 4u;
            o[0] = v0;
            o[1] = v1;
            o[2] = v2;
            o[3] = v3;
        }
    }
}

extern "C" void kernel_launch(void* const* d_in, const int* in_sizes, int n_in,
                              void* d_out, int out_size)
{
    const float4* codebooks = (const float4*)d_in[0];  // [2,256,4] fp32
    const float*  scales    = (const float*) d_in[1];  // [numel/64, 1] fp32
    const int4*   codes     = (const int4*)  d_in[2];  // [2, numel/8] int32
    float4*       out       = (float4*)d_out;          // [8192, 8192] fp32

    dequant_kernel<<<NCTA, TPB>>>(codebooks, scales, codes, out);
}